// round 5
// baseline (speedup 1.0000x reference)
#include <cuda_runtime.h>
#include <cuda_bf16.h>
#include <cstdint>

#define NNODES 100000
#define HD 128
#define ROW 640      // 5*HD
#define LMAX 262144
#define MAXE 32      // records staged per smem tile

// scratch
__device__ int    g_cnt[2 * NNODES];
__device__ int    g_off[2 * NNODES];
__device__ int    g_cur[2 * NNODES];
__device__ float  g_inv[2 * NNODES];
// sorted per-(side,position) event records: 2 float4s each.
// rec[2p+0] = {bits(e), bits(other), s0, c1}   rec[2p+1] = {cm, cb, x, pad}
__device__ float4 g_rec[4 * LMAX];

// ---------------------------------------------------------------------------
// fast cos: Cody-Waite FMA reduction + cephes minimax polys. |x|<=~1000 here.
// ---------------------------------------------------------------------------
__device__ __forceinline__ float fast_cos(float x) {
    float j = rintf(x * 0.63661977236758134f);
    int   q = (int)j;
    float r = fmaf(j, -1.5707963705062866f, x);
    r = fmaf(j, 4.3711390e-8f, r);
    float r2 = r * r;
    float ps = fmaf(r2, -1.9515295891e-4f, 8.3321608736e-3f);
    ps = fmaf(r2, ps, -1.6666654611e-1f);
    float s  = fmaf(r * r2, ps, r);
    float pc = fmaf(r2, 2.443315711809948e-5f, -1.388731625493765e-3f);
    pc = fmaf(r2, pc, 4.166664568298827e-2f);
    pc = fmaf(r2, pc, -0.5f);
    float c  = fmaf(r2, pc, 1.0f);
    float v = (q & 1) ? s : c;
    if ((q + 1) & 2) v = -v;
    return v;
}

// ---------------------------------------------------------------------------
__global__ void k_init() {
    int i = blockIdx.x * blockDim.x + threadIdx.x;
    if (i < 2 * NNODES) g_cnt[i] = 0;
}

__global__ void k_count(const int* __restrict__ src, const int* __restrict__ dst,
                        int L) {
    int i = blockIdx.x * blockDim.x + threadIdx.x;
    if (i >= L) return;
    atomicAdd(&g_cnt[src[i]], 1);
    atomicAdd(&g_cnt[NNODES + dst[i]], 1);
}

// exclusive scan of counts -> offsets; zero cursors; inverse counts.
__global__ void k_scan() {
    const int base  = blockIdx.x * NNODES;
    const int chunk = (NNODES + 1023) / 1024;
    int t  = threadIdx.x;
    int s0 = t * chunk;
    int s1 = min(s0 + chunk, NNODES);
    int sum = 0;
    for (int i = s0; i < s1; i++) sum += g_cnt[base + i];
    __shared__ int sh[1024];
    sh[t] = sum;
    __syncthreads();
    for (int d = 1; d < 1024; d <<= 1) {
        int v = 0;
        if (t >= d) v = sh[t - d];
        __syncthreads();
        if (t >= d) sh[t] += v;
        __syncthreads();
    }
    int excl = (t == 0) ? 0 : sh[t - 1];
    for (int i = s0; i < s1; i++) {
        int c = g_cnt[base + i];
        g_off[base + i] = excl;
        g_cur[base + i] = 0;
        g_inv[base + i] = 1.0f / (float)max(c, 1);
        excl += c;
    }
}

// counting-sort fill: write fully-precomputed records at sorted positions.
__global__ void k_fill(const int* __restrict__ type, const int* __restrict__ src,
                       const float* __restrict__ sm, const int* __restrict__ dst,
                       const float* __restrict__ dm, const float* __restrict__ em,
                       const float* __restrict__ ts, const float* __restrict__ lu,
                       int L) {
    int i = blockIdx.x * blockDim.x + threadIdx.x;
    if (i >= L) return;
    int   s   = src[i], d = dst[i];
    float smv = sm[i], dmv = dm[i], emv = em[i], t = ts[i];
    float ty  = (float)type[i];
    float lus = __ldg(lu + s), lud = __ldg(lu + d);

    // src side: message scale cb = event_mask
    int p = atomicAdd(&g_cur[s], 1) + g_off[s];
    g_rec[2 * p]     = make_float4(__int_as_float(i), __int_as_float(d),
                                   ty * emv, smv * emv);
    g_rec[2 * p + 1] = make_float4(dmv * emv, emv, t - lus * dmv, 0.0f);

    // dst side: cb = dst_mask (faithful: lu*dst_mask both sides)
    p = atomicAdd(&g_cur[NNODES + d], 1) + g_off[NNODES + d] + LMAX;
    g_rec[2 * p]     = make_float4(__int_as_float(i), __int_as_float(s),
                                   ty * dmv, dmv * dmv);
    g_rec[2 * p + 1] = make_float4(smv * dmv, dmv, t - lud * dmv, 0.0f);
}

// ---------------------------------------------------------------------------
// gather: one 128-thread block per (side,node); thread owns one h. Records
// staged through smem (coalesced), 4-wide unrolled gathers for MLP, scalar
// per-thread state (no spills). Row written exactly once.
// ---------------------------------------------------------------------------
__global__ void __launch_bounds__(128)
k_gather(const float* __restrict__ E, const float* __restrict__ M,
         const float* __restrict__ w, const float* __restrict__ b,
         float* __restrict__ out) {
    __shared__ float4 srec[2 * MAXE];
    int  slot  = blockIdx.x;
    int  h     = threadIdx.x;
    bool dside = slot >= NNODES;
    int  n     = dside ? slot - NNODES : slot;

    int   off = g_off[slot] + (dside ? LMAX : 0);
    int   cnt = g_cnt[slot];
    float inv = g_inv[slot];
    float wv  = __ldg(w + h), bv = __ldg(b + h);

    float a0 = 0.f, a1 = 0.f, a2 = 0.f, a3 = 0.f, a4 = 0.f;

    for (int base = 0; base < cnt; base += MAXE) {
        int tile = min(cnt - base, MAXE);
        if (h < 2 * tile) srec[h] = g_rec[2 * (off + base) + h];
        __syncthreads();

        int j = 0;
        for (; j + 4 <= tile; j += 4) {
            float4 ra0 = srec[2*j],   rb0 = srec[2*j+1];
            float4 ra1 = srec[2*j+2], rb1 = srec[2*j+3];
            float4 ra2 = srec[2*j+4], rb2 = srec[2*j+5];
            float4 ra3 = srec[2*j+6], rb3 = srec[2*j+7];
            // issue all 8 gathers before any use
            float Ev0 = __ldg(E + (size_t)__float_as_int(ra0.x) * HD + h);
            float Ev1 = __ldg(E + (size_t)__float_as_int(ra1.x) * HD + h);
            float Ev2 = __ldg(E + (size_t)__float_as_int(ra2.x) * HD + h);
            float Ev3 = __ldg(E + (size_t)__float_as_int(ra3.x) * HD + h);
            float Mv0 = __ldg(M + (size_t)__float_as_int(ra0.y) * HD + h);
            float Mv1 = __ldg(M + (size_t)__float_as_int(ra1.y) * HD + h);
            float Mv2 = __ldg(M + (size_t)__float_as_int(ra2.y) * HD + h);
            float Mv3 = __ldg(M + (size_t)__float_as_int(ra3.y) * HD + h);
            a0 += (ra0.z + ra1.z) + (ra2.z + ra3.z);
            a1 += (ra0.w + ra1.w) + (ra2.w + ra3.w);
            a3 = fmaf(fast_cos(fmaf(rb0.z, wv, bv)), rb0.y, a3);
            a3 = fmaf(fast_cos(fmaf(rb1.z, wv, bv)), rb1.y, a3);
            a3 = fmaf(fast_cos(fmaf(rb2.z, wv, bv)), rb2.y, a3);
            a3 = fmaf(fast_cos(fmaf(rb3.z, wv, bv)), rb3.y, a3);
            a2 = fmaf(Mv0, rb0.x, a2); a4 = fmaf(Ev0, rb0.y, a4);
            a2 = fmaf(Mv1, rb1.x, a2); a4 = fmaf(Ev1, rb1.y, a4);
            a2 = fmaf(Mv2, rb2.x, a2); a4 = fmaf(Ev2, rb2.y, a4);
            a2 = fmaf(Mv3, rb3.x, a2); a4 = fmaf(Ev3, rb3.y, a4);
        }
        for (; j < tile; j++) {
            float4 ra = srec[2*j], rb = srec[2*j+1];
            float Ev = __ldg(E + (size_t)__float_as_int(ra.x) * HD + h);
            float Mv = __ldg(M + (size_t)__float_as_int(ra.y) * HD + h);
            a0 += ra.z;
            a1 += ra.w;
            a3 = fmaf(fast_cos(fmaf(rb.z, wv, bv)), rb.y, a3);
            a2 = fmaf(Mv, rb.x, a2);
            a4 = fmaf(Ev, rb.y, a4);
        }
        __syncthreads();
    }

    float mv = __ldg(M + (size_t)n * HD + h);
    float* o = out + (size_t)slot * ROW;
    o[h]       = a0 * inv;
    o[128 + h] = mv * (a1 * inv);
    o[256 + h] = a2 * inv;
    o[384 + h] = a3 * inv;
    o[512 + h] = a4 * inv;
}

// ---------------------------------------------------------------------------
extern "C" void kernel_launch(void* const* d_in, const int* in_sizes, int n_in,
                              void* d_out, int out_size) {
    const int*   type = (const int*)  d_in[0];
    const int*   src  = (const int*)  d_in[1];
    const float* smk  = (const float*)d_in[2];
    const int*   dst  = (const int*)  d_in[3];
    const float* dmk  = (const float*)d_in[4];
    const float* E    = (const float*)d_in[5];
    const float* em   = (const float*)d_in[6];
    const float* ts   = (const float*)d_in[7];
    const float* mem  = (const float*)d_in[8];
    const float* lu   = (const float*)d_in[9];
    const float* w    = (const float*)d_in[10];
    const float* b    = (const float*)d_in[11];
    float* out = (float*)d_out;
    int L = in_sizes[0];
    if (L > LMAX) L = LMAX;

    k_init <<<(2 * NNODES + 255) / 256, 256>>>();
    k_count<<<(L + 255) / 256, 256>>>(src, dst, L);
    k_scan <<<2, 1024>>>();
    k_fill <<<(L + 255) / 256, 256>>>(type, src, smk, dst, dmk, em, ts, lu, L);
    k_gather<<<2 * NNODES, 128>>>(E, mem, w, b, out);
}